// round 1
// baseline (speedup 1.0000x reference)
#include <cuda_runtime.h>

// Correlation volume, integer-shift formulation:
//   out[n, k=9*i+j, h, w] = sum_z A[n,z,h,w] * B[n,z, h+j-4, w+i-4]  (zero pad)
// N=8, Z=128, H=W=160, 81 displacements.

#define N_  8
#define Z_  128
#define H_  160
#define W_  160
#define TH  16
#define TW  16
#define ZC  8           // z-slices per smem chunk
#define BROWS 24        // TH + 8
#define BCOLS 24        // TW + 8
#define BSTRIDE 25      // pad to reduce bank conflicts

__global__ __launch_bounds__(192, 2)
void corr_kernel(const float* __restrict__ A,
                 const float* __restrict__ B,
                 float* __restrict__ out)
{
    __shared__ float As[ZC][TH][TW];
    __shared__ float Bs[ZC][BROWS][BSTRIDE];

    const int tx = threadIdx.x;   // 0..7  (pixel pair along w)
    const int ty = threadIdx.y;   // 0..7  (pixel pair along h)
    const int kz = threadIdx.z;   // 0..2  (i-group: i = 3*kz + il)
    const int tid = tx + 8 * ty + 64 * kz;   // 0..191

    const int w0 = blockIdx.x * TW;
    const int h0 = blockIdx.y * TH;
    const int n  = blockIdx.z;

    const size_t plane = (size_t)H_ * W_;
    const float* Abase = A + (size_t)n * Z_ * plane;
    const float* Bbase = B + (size_t)n * Z_ * plane;

    // accumulators: acc[py][px][il*9 + j]
    float acc[2][2][27];
    #pragma unroll
    for (int py = 0; py < 2; py++)
        #pragma unroll
        for (int px = 0; px < 2; px++)
            #pragma unroll
            for (int q = 0; q < 27; q++)
                acc[py][px][q] = 0.0f;

    for (int zc = 0; zc < Z_; zc += ZC) {
        __syncthreads();

        // ---- load A chunk: ZC*16*16 = 2048 floats as 512 float4 ----
        for (int idx = tid; idx < ZC * TH * TW / 4; idx += 192) {
            int z   = idx >> 6;          // / 64
            int rem = idx & 63;
            int r   = rem >> 2;          // row
            int c4  = rem & 3;           // float4 within row
            float4 v = *(const float4*)(Abase + (size_t)(zc + z) * plane
                                        + (size_t)(h0 + r) * W_ + w0 + c4 * 4);
            *(float4*)&As[z][r][c4 * 4] = v;
        }

        // ---- load B chunk: ZC*24*24 = 4608 floats, zero-padded at borders ----
        for (int idx = tid; idx < ZC * BROWS * BCOLS; idx += 192) {
            int z   = idx / (BROWS * BCOLS);
            int rem = idx % (BROWS * BCOLS);
            int r   = rem / BCOLS;
            int c   = rem % BCOLS;
            int gh = h0 - 4 + r;
            int gw = w0 - 4 + c;
            float v = 0.0f;
            if (gh >= 0 && gh < H_ && gw >= 0 && gw < W_)
                v = Bbase[(size_t)(zc + z) * plane + (size_t)gh * W_ + gw];
            Bs[z][r][c] = v;
        }
        __syncthreads();

        // ---- compute ----
        #pragma unroll 2
        for (int z = 0; z < ZC; z++) {
            const float a00 = As[z][2 * ty    ][2 * tx    ];
            const float a01 = As[z][2 * ty    ][2 * tx + 1];
            const float a10 = As[z][2 * ty + 1][2 * tx    ];
            const float a11 = As[z][2 * ty + 1][2 * tx + 1];

            #pragma unroll
            for (int r = 0; r < 10; r++) {      // B-tile row = 2*ty + r
                float b[4];
                #pragma unroll
                for (int c = 0; c < 4; c++)
                    b[c] = Bs[z][2 * ty + r][2 * tx + 3 * kz + c];

                #pragma unroll
                for (int il = 0; il < 3; il++) {
                    if (r <= 8) {               // py = 0, j = r
                        acc[0][0][il * 9 + r] += a00 * b[il];
                        acc[0][1][il * 9 + r] += a01 * b[il + 1];
                    }
                    if (r >= 1) {               // py = 1, j = r - 1
                        acc[1][0][il * 9 + r - 1] += a10 * b[il];
                        acc[1][1][il * 9 + r - 1] += a11 * b[il + 1];
                    }
                }
            }
        }
    }

    // ---- write out: k = (3*kz+il)*9 + j, 2 float2 stores per k ----
    const int h = h0 + 2 * ty;
    const int w = w0 + 2 * tx;
    #pragma unroll
    for (int il = 0; il < 3; il++) {
        #pragma unroll
        for (int j = 0; j < 9; j++) {
            const int k = (3 * kz + il) * 9 + j;
            size_t base = (((size_t)n * 81 + k) * H_ + h) * W_ + w;
            float2 v0 = make_float2(acc[0][0][il * 9 + j], acc[0][1][il * 9 + j]);
            float2 v1 = make_float2(acc[1][0][il * 9 + j], acc[1][1][il * 9 + j]);
            *(float2*)(out + base)      = v0;
            *(float2*)(out + base + W_) = v1;
        }
    }
}

extern "C" void kernel_launch(void* const* d_in, const int* in_sizes, int n_in,
                              void* d_out, int out_size)
{
    const float* imgA = (const float*)d_in[0];
    const float* imgB = (const float*)d_in[1];
    float* out = (float*)d_out;

    dim3 block(8, 8, 3);
    dim3 grid(W_ / TW, H_ / TH, N_);
    corr_kernel<<<grid, block>>>(imgA, imgB, out);
}